// round 12
// baseline (speedup 1.0000x reference)
#include <cuda_runtime.h>
#include <math.h>
#include <cfloat>

#define BB 8
#define QQ 2048
#define GG 128
#define CC 512
#define NT 128
#define NW (NT/32)           // 4 warps
#define NCH 4                // column chunks (512 cols each)
#define CHW 512              // chunk width
#define CP 16                // columns per thread (4 chunks x 4 contiguous)
#define MAXPATH 140          // path entries: dummy + <=G matched + slack

typedef unsigned long long u64;

// ---------------- device scratch (no allocation allowed) ----------------
__device__ float g_ct[BB*GG*QQ];   // transposed cost: CT[b][g][q]  (8 MB)
__device__ int   g_labels[BB*GG];
__device__ int   g_na[BB];

// ---------------- prep: normalize int inputs (int32 vs int64 on disk) ----
__global__ void prep_kernel(const int* __restrict__ lab_raw,
                            const int* __restrict__ na_raw) {
    __shared__ int nzl, nzn;
    int t = threadIdx.x;
    if (t == 0) { nzl = 0; nzn = 0; }
    __syncthreads();
    for (int k = t; k < (BB*GG)/2; k += blockDim.x)
        if (lab_raw[2*k+1] != 0) atomicExch(&nzl, 1);
    for (int k = t; k < BB/2; k += blockDim.x)
        if (na_raw[2*k+1] != 0) atomicExch(&nzn, 1);
    __syncthreads();
    bool l64 = (nzl == 0), n64 = (nzn == 0);
    for (int k = t; k < BB*GG; k += blockDim.x)
        g_labels[k] = l64 ? lab_raw[2*k] : lab_raw[k];
    if (t < BB)
        g_na[t] = n64 ? na_raw[2*t] : na_raw[t];
}

// ------- fused cost + transpose: fc[b][q][g] and CT[b][g][q] in one pass -----
__global__ void cost_transpose_kernel(const float* __restrict__ sem,
                                      const float* __restrict__ center,
                                      const float* __restrict__ sizes,
                                      const float* __restrict__ gious,
                                      float* __restrict__ fc) {
    __shared__ float tile[32][33];
    int b = blockIdx.z;
    int q0 = blockIdx.x * 32, g0 = blockIdx.y * 32;
    int x = threadIdx.x;
    int g = g0 + x;
    int lab = g_labels[b*GG + g];
    for (int r = threadIdx.y; r < 32; r += 8) {
        int q = q0 + r;
        float s = sem[((size_t)(b*QQ + q))*CC + lab];
        // XLA lowers lax.logistic as 0.5 + 0.5*tanh(0.5*x)
        float p = 0.5f + 0.5f * tanhf(0.5f * s);
        float pos = 0.25f * (1.0f - p) * (1.0f - p) * (-logf(p + 1e-8f));
        float neg = 0.75f * p * p * (-log1pf(-(p - 1e-8f)));
        float diff = pos - neg;
        size_t idx = ((size_t)(b*QQ + q))*GG + g;
        float val = 2.0f*diff + 5.0f*center[idx] + 1.0f*sizes[idx] - 2.0f*gious[idx];
        fc[idx] = val;                 // coalesced along g
        tile[r][x] = val;
    }
    __syncthreads();
    for (int r = threadIdx.y; r < 32; r += 8)
        g_ct[((size_t)(b*GG + g0 + r))*QQ + q0 + x] = tile[x][r];  // coalesced along q
}

// --------- order-preserving keys (monotone) -----------------------------
__device__ __forceinline__ unsigned fkey(float f) {
    unsigned u = __float_as_uint(f);
    return (u & 0x80000000u) ? ~u : (u | 0x80000000u);
}
__device__ __forceinline__ float finv(unsigned k) {
    unsigned u = (k & 0x80000000u) ? (k & 0x7fffffffu) : ~k;
    return __uint_as_float(u);
}
__device__ __forceinline__ u64 dkey(double d) {
    u64 b = (u64)__double_as_longlong(d);
    return (b & 0x8000000000000000ull) ? ~b : (b | 0x8000000000000000ull);
}

// ---------------- LSA: exact replica of the reference's algorithm -------
// R10 structure (exact fp32-min threshold key + packed exact-local-argmin
// key, two REDUX; balanced trees; atomicMin-u64 winner; 2 barriers) plus
// speculative u prefetch: the common bj==gj case starts the next scan from
// registers with no dependent LDS after B2.
__global__ void __launch_bounds__(NT, 1) lsa_kernel(float* __restrict__ out_inds,
                                                    float* __restrict__ out_mask) {
    __shared__ double v[QQ];            // fp64 master potentials (0-based cols)
    __shared__ __align__(16) float vf[QQ];  // fp32 shadow master
    __shared__ double u[GG + 1];        // rows 1..GG
    __shared__ short  p[QQ];            // matched row per col (0 = free)
    __shared__ unsigned short ulist[MAXPATH];
    __shared__ double sdelta[MAXPATH];
    __shared__ __align__(16) unsigned swm[NW];   // per-warp exact fp32 min key
    __shared__ __align__(16) unsigned swp[NW];   // per-warp (key21|col11) min
    __shared__ double cval[QQ];         // exact fp64 reduced cost of posted cols
    __shared__ u64 slot[2];             // ping-pong winner keys

    int b = blockIdx.x;
    int tid = threadIdx.x;
    int lane = tid & 31, wid = tid >> 5;
    const float* CT = g_ct + (size_t)b * GG * QQ;
    const int cbase = tid << 2;         // my 4 cols within each chunk start here

    int na = g_na[b];
    if (na < 0) na = 0;
    if (na > GG) na = GG;

    for (int jj = tid; jj < QQ; jj += NT) { v[jj] = 0.0; vf[jj] = 0.0f; p[jj] = 0; }
    for (int jj = tid; jj <= GG; jj += NT) u[jj] = 0.0;
    if (tid == 0) { ulist[0] = 0; slot[0] = ~0ull; slot[1] = ~0ull; }
    __syncthreads();

    float r[CP], w[CP], c[CP];
    #pragma unroll
    for (int k = 0; k < CP; k++) { r[k] = 0.f; w[k] = 0.f; }
    int pre_i0 = -1;
    int it = 0;                         // global iteration parity counter

    if (na > 0) {                        // warm prefetch: row 1
        #pragma unroll
        for (int ch = 0; ch < NCH; ch++) {
            float4 t = *(const float4*)(CT + ch*CHW + cbase);
            r[ch*4+0] = t.x; r[ch*4+1] = t.y; r[ch*4+2] = t.z; r[ch*4+3] = t.w;
        }
        pre_i0 = 1;
    }

    for (int i = 1; i <= na; i++) {
        int cnt = 1;                    // path length incl. dummy (redundant)
        int i0 = i;
        double ui = u[i];
        float uif = (float)ui;
        int fbj = 0;

        for (;;) {
            if (pre_i0 != i0) {         // mispredict: synchronous reload (uniform)
                const float* row = CT + (size_t)(i0 - 1) * QQ;
                #pragma unroll
                for (int ch = 0; ch < NCH; ch++) {
                    float4 t = *(const float4*)(row + ch*CHW + cbase);
                    r[ch*4+0] = t.x; r[ch*4+1] = t.y; r[ch*4+2] = t.z; r[ch*4+3] = t.w;
                }
                pre_i0 = i0;
            }

            // ---- phase 1: register scan + balanced min / argmin trees ----
            #pragma unroll
            for (int k = 0; k < CP; k++) c[k] = (r[k] - uif) - w[k];
            float t8[8];
            #pragma unroll
            for (int k = 0; k < 8; k++) t8[k] = fminf(c[2*k], c[2*k+1]);
            float t4a = fminf(t8[0], t8[1]), t4b = fminf(t8[2], t8[3]);
            float t4c = fminf(t8[4], t8[5]), t4d = fminf(t8[6], t8[7]);
            float m = fminf(fminf(t4a, t4b), fminf(t4c, t4d));
            int e[CP];
            #pragma unroll
            for (int k = 0; k < CP; k++) {
                int col = (k >> 2)*CHW + cbase + (k & 3);
                e[k] = (c[k] == m) ? col : 0x7FF;
            }
            int s8[8];
            #pragma unroll
            for (int k = 0; k < 8; k++) s8[k] = min(e[2*k], e[2*k+1]);
            int s4a = min(s8[0], s8[1]), s4b = min(s8[2], s8[3]);
            int s4c = min(s8[4], s8[5]), s4d = min(s8[6], s8[7]);
            int mj = min(min(s4a, s4b), min(s4c, s4d));

            unsigned km = fkey(m);
            unsigned kp = (km & 0xFFFFF800u) | (unsigned)mj;  // 21b key | 11b col
            unsigned wkm = __reduce_min_sync(0xffffffffu, km);
            unsigned wkp = __reduce_min_sync(0xffffffffu, kp);
            if (lane == 0) { swm[wid] = wkm; swp[wid] = wkp; }
            __syncthreads();            // B1

            // ---- phase 2: fold, speculate row+u, post candidates ----
            uint4 ma = *(const uint4*)&swm[0];
            uint4 pa = *(const uint4*)&swp[0];
            unsigned gm_ = umin(umin(ma.x, ma.y), umin(ma.z, ma.w));
            unsigned gp_ = umin(umin(pa.x, pa.y), umin(pa.z, pa.w));

            int gj = (int)(gp_ & 0x7FFu);             // approx fp32 argmin col
            int pg = p[gj];
            int spec = (pg == 0) ? ((i < na) ? (i + 1) : i0) : pg;
            double u_spec = u[spec];                  // speculative next ui (overlapped)

            float thr = finv(gm_) + 1e-3f;            // EXACT fp32 min + margin
            if (m <= thr) {
                double uid = ui;
                #pragma unroll
                for (int k = 0; k < CP; k++) {
                    if (c[k] <= thr) {
                        int col = (k >> 2)*CHW + cbase + (k & 3);
                        double cd = ((double)r[k] - uid) - v[col];
                        cval[col] = cd;               // exact value (distinct cols)
                        atomicMin(&slot[it & 1], (dkey(cd) & ~0x7FFull) | (u64)col);
                    }
                }
            }
            if (tid == 32) slot[(it + 1) & 1] = ~0ull;  // reset other slot (warp 1)

            {                                          // speculative row load into r[]
                const float* rs = CT + (size_t)(spec - 1) * QQ;
                #pragma unroll
                for (int ch = 0; ch < NCH; ch++) {
                    float4 t = *(const float4*)(rs + ch*CHW + cbase);
                    r[ch*4+0] = t.x; r[ch*4+1] = t.y; r[ch*4+2] = t.z; r[ch*4+3] = t.w;
                }
                pre_i0 = spec;
            }
            __syncthreads();            // B2

            // ---- phase 3: decode winner; common case uses speculated state ----
            u64 win = slot[it & 1];
            it++;
            int bj = (int)(win & 0x7FFull);
            bool hit = (bj == gj);
            int pb = hit ? pg : p[bj];
            if (tid == 0) sdelta[cnt - 1] = cval[bj];  // off critical path (tid0 only)

            if (pb == 0) {
                fbj = bj;               // way==0 => single-step backtrack
                break;                  // r[] holds next search's row if hit
            }
            if (tid == 0) ulist[cnt] = (unsigned short)bj;
            cnt++;
            i0 = pb;
            ui = hit ? u_spec : u[pb];
            uif = (float)ui;
            {                            // mark used locally if one of my cols
                int o = bj - cbase;
                #pragma unroll
                for (int k = 0; k < CP; k++)
                    if (o == (k >> 2)*CHW + (k & 3)) w[k] = -FLT_MAX;
            }
        }

        __syncthreads();                // S1: ulist/sdelta writes visible

        // ---- parallel bit-exact write-back: entry k gets deltas k..cnt-1 ----
        if (tid < cnt) {
            if (tid == 0) {              // dummy column: u[i] only (v[dummy] never read)
                double uu = u[i];
                for (int t = 0; t < cnt; t++) uu += sdelta[t];
                u[i] = uu;
            } else {
                int col = ulist[tid];
                int ik = p[col];
                double uu = u[ik];
                double vv = v[col];
                for (int t = tid; t < cnt; t++) {     // ascending t == reference order
                    double d = sdelta[t];
                    uu += d;
                    vv -= d;
                }
                u[ik] = uu;
                v[col] = vv;
                vf[col] = (float)vv;     // restore shadow master
            }
        }
        if (tid == 0) p[fbj] = (short)i;              // assign final unmatched column
        __syncthreads();                // S2: write-back visible

        // refresh register shadow (clears sentinels, picks up new v values)
        #pragma unroll
        for (int ch = 0; ch < NCH; ch++) {
            float4 t = *(const float4*)(vf + ch*CHW + cbase);
            w[ch*4+0] = t.x; w[ch*4+1] = t.y; w[ch*4+2] = t.z; w[ch*4+3] = t.w;
        }
    }

    // outputs: proposal col matched to gt p[col]-1
    for (int jj = tid; jj < QQ; jj += NT) {
        int pj = p[jj];
        size_t o = (size_t)b * QQ + jj;
        out_inds[o] = (pj > 0) ? (float)(pj - 1) : 0.0f;
        out_mask[o] = (pj > 0) ? 1.0f : 0.0f;
    }
}

// ---------------- launch ------------------------------------------------
extern "C" void kernel_launch(void* const* d_in, const int* in_sizes, int n_in,
                              void* d_out, int out_size) {
    const float* sem    = (const float*)d_in[0];
    const float* center = (const float*)d_in[1];
    const float* sizes  = (const float*)d_in[2];
    const float* gious  = (const float*)d_in[3];
    const int*   labels = (const int*)d_in[4];
    const int*   na     = (const int*)d_in[5];

    float* out      = (float*)d_out;
    float* out_inds = out;
    float* out_mask = out + (size_t)BB * QQ;
    float* fc       = out + (size_t)2 * BB * QQ;   // final_cost region

    prep_kernel<<<1, 512>>>(labels, na);
    cost_transpose_kernel<<<dim3(QQ/32, GG/32, BB), dim3(32, 8)>>>(sem, center, sizes, gious, fc);
    lsa_kernel<<<BB, NT>>>(out_inds, out_mask);
}

// round 13
// speedup vs baseline: 1.0599x; 1.0599x over previous
#include <cuda_runtime.h>
#include <math.h>
#include <cfloat>

#define BB 8
#define QQ 2048
#define GG 128
#define CC 512
#define NT 128
#define NW (NT/32)           // 4 warps
#define NCH 4                // column chunks (512 cols each)
#define CHW 512              // chunk width
#define CP 16                // columns per thread (4 chunks x 4 contiguous)
#define MAXPATH 140          // path entries: dummy + <=G matched + slack

typedef unsigned long long u64;

// ---------------- device scratch (no allocation allowed) ----------------
__device__ float g_ct[BB*GG*QQ];   // transposed cost: CT[b][g][q]  (8 MB)
__device__ int   g_labels[BB*GG];
__device__ int   g_na[BB];

// ---------------- prep: normalize int inputs (int32 vs int64 on disk) ----
__global__ void prep_kernel(const int* __restrict__ lab_raw,
                            const int* __restrict__ na_raw) {
    __shared__ int nzl, nzn;
    int t = threadIdx.x;
    if (t == 0) { nzl = 0; nzn = 0; }
    __syncthreads();
    for (int k = t; k < (BB*GG)/2; k += blockDim.x)
        if (lab_raw[2*k+1] != 0) atomicExch(&nzl, 1);
    for (int k = t; k < BB/2; k += blockDim.x)
        if (na_raw[2*k+1] != 0) atomicExch(&nzn, 1);
    __syncthreads();
    bool l64 = (nzl == 0), n64 = (nzn == 0);
    for (int k = t; k < BB*GG; k += blockDim.x)
        g_labels[k] = l64 ? lab_raw[2*k] : lab_raw[k];
    if (t < BB)
        g_na[t] = n64 ? na_raw[2*t] : na_raw[t];
}

// ------- fused cost + transpose: fc[b][q][g] and CT[b][g][q] in one pass -----
__global__ void cost_transpose_kernel(const float* __restrict__ sem,
                                      const float* __restrict__ center,
                                      const float* __restrict__ sizes,
                                      const float* __restrict__ gious,
                                      float* __restrict__ fc) {
    __shared__ float tile[32][33];
    int b = blockIdx.z;
    int q0 = blockIdx.x * 32, g0 = blockIdx.y * 32;
    int x = threadIdx.x;
    int g = g0 + x;
    int lab = g_labels[b*GG + g];
    for (int r = threadIdx.y; r < 32; r += 8) {
        int q = q0 + r;
        float s = sem[((size_t)(b*QQ + q))*CC + lab];
        // XLA lowers lax.logistic as 0.5 + 0.5*tanh(0.5*x)
        float p = 0.5f + 0.5f * tanhf(0.5f * s);
        float pos = 0.25f * (1.0f - p) * (1.0f - p) * (-logf(p + 1e-8f));
        float neg = 0.75f * p * p * (-log1pf(-(p - 1e-8f)));
        float diff = pos - neg;
        size_t idx = ((size_t)(b*QQ + q))*GG + g;
        float val = 2.0f*diff + 5.0f*center[idx] + 1.0f*sizes[idx] - 2.0f*gious[idx];
        fc[idx] = val;                 // coalesced along g
        tile[r][x] = val;
    }
    __syncthreads();
    for (int r = threadIdx.y; r < 32; r += 8)
        g_ct[((size_t)(b*GG + g0 + r))*QQ + q0 + x] = tile[x][r];  // coalesced along q
}

// --------- order-preserving keys (monotone) -----------------------------
__device__ __forceinline__ unsigned fkey(float f) {
    unsigned u = __float_as_uint(f);
    return (u & 0x80000000u) ? ~u : (u | 0x80000000u);
}
__device__ __forceinline__ float finv(unsigned k) {
    unsigned u = (k & 0x80000000u) ? (k & 0x7fffffffu) : ~k;
    return __uint_as_float(u);
}
__device__ __forceinline__ u64 dkey(double d) {
    u64 b = (u64)__double_as_longlong(d);
    return (b & 0x8000000000000000ull) ? ~b : (b | 0x8000000000000000ull);
}

// ---------------- LSA: exact replica of the reference's algorithm -------
// R10 structure (two exact-key REDUX, balanced trees, atomicMin-u64 winner,
// 2 barriers, speculative row prefetch, lazy-delta bit-exact write-back)
// with the u[i0] term REMOVED from the fp32 scan: it is a per-row constant,
// so it cannot change the argmin or the threshold-relative candidate set;
// the exact fp64 verification (which does include u[i0]) is unchanged.
// This takes u[] off the scan's dependency chain entirely.
__global__ void __launch_bounds__(NT, 1) lsa_kernel(float* __restrict__ out_inds,
                                                    float* __restrict__ out_mask) {
    __shared__ double v[QQ];            // fp64 master potentials (0-based cols)
    __shared__ __align__(16) float vf[QQ];  // fp32 shadow master
    __shared__ double u[GG + 1];        // rows 1..GG
    __shared__ short  p[QQ];            // matched row per col (0 = free)
    __shared__ unsigned short ulist[MAXPATH];
    __shared__ double sdelta[MAXPATH];
    __shared__ __align__(16) unsigned swm[NW];   // per-warp exact fp32 min key
    __shared__ __align__(16) unsigned swp[NW];   // per-warp (key21|col11) min
    __shared__ double cval[QQ];         // exact fp64 reduced cost of posted cols
    __shared__ u64 slot[2];             // ping-pong winner keys

    int b = blockIdx.x;
    int tid = threadIdx.x;
    int lane = tid & 31, wid = tid >> 5;
    const float* CT = g_ct + (size_t)b * GG * QQ;
    const int cbase = tid << 2;         // my 4 cols within each chunk start here

    int na = g_na[b];
    if (na < 0) na = 0;
    if (na > GG) na = GG;

    for (int jj = tid; jj < QQ; jj += NT) { v[jj] = 0.0; vf[jj] = 0.0f; p[jj] = 0; }
    for (int jj = tid; jj <= GG; jj += NT) u[jj] = 0.0;
    if (tid == 0) { ulist[0] = 0; slot[0] = ~0ull; slot[1] = ~0ull; }
    __syncthreads();

    float r[CP], w[CP], c[CP];
    #pragma unroll
    for (int k = 0; k < CP; k++) { r[k] = 0.f; w[k] = 0.f; }
    int pre_i0 = -1;
    int it = 0;                         // global iteration parity counter

    if (na > 0) {                        // warm prefetch: row 1
        #pragma unroll
        for (int ch = 0; ch < NCH; ch++) {
            float4 t = *(const float4*)(CT + ch*CHW + cbase);
            r[ch*4+0] = t.x; r[ch*4+1] = t.y; r[ch*4+2] = t.z; r[ch*4+3] = t.w;
        }
        pre_i0 = 1;
    }

    for (int i = 1; i <= na; i++) {
        int cnt = 1;                    // path length incl. dummy (redundant)
        int i0 = i;
        double ui = u[i];               // needed only for fp64 candidate posts
        int fbj = 0;

        for (;;) {
            if (pre_i0 != i0) {         // mispredict: synchronous reload (uniform)
                const float* row = CT + (size_t)(i0 - 1) * QQ;
                #pragma unroll
                for (int ch = 0; ch < NCH; ch++) {
                    float4 t = *(const float4*)(row + ch*CHW + cbase);
                    r[ch*4+0] = t.x; r[ch*4+1] = t.y; r[ch*4+2] = t.z; r[ch*4+3] = t.w;
                }
                pre_i0 = i0;
            }

            // ---- phase 1: register scan (NO u term) + balanced trees ----
            #pragma unroll
            for (int k = 0; k < CP; k++) c[k] = r[k] - w[k];
            float t8[8];
            #pragma unroll
            for (int k = 0; k < 8; k++) t8[k] = fminf(c[2*k], c[2*k+1]);
            float t4a = fminf(t8[0], t8[1]), t4b = fminf(t8[2], t8[3]);
            float t4c = fminf(t8[4], t8[5]), t4d = fminf(t8[6], t8[7]);
            float m = fminf(fminf(t4a, t4b), fminf(t4c, t4d));
            int e[CP];
            #pragma unroll
            for (int k = 0; k < CP; k++) {
                int col = (k >> 2)*CHW + cbase + (k & 3);
                e[k] = (c[k] == m) ? col : 0x7FF;
            }
            int s8[8];
            #pragma unroll
            for (int k = 0; k < 8; k++) s8[k] = min(e[2*k], e[2*k+1]);
            int s4a = min(s8[0], s8[1]), s4b = min(s8[2], s8[3]);
            int s4c = min(s8[4], s8[5]), s4d = min(s8[6], s8[7]);
            int mj = min(min(s4a, s4b), min(s4c, s4d));

            unsigned km = fkey(m);
            unsigned kp = (km & 0xFFFFF800u) | (unsigned)mj;  // 21b key | 11b col
            unsigned wkm = __reduce_min_sync(0xffffffffu, km);
            unsigned wkp = __reduce_min_sync(0xffffffffu, kp);
            if (lane == 0) { swm[wid] = wkm; swp[wid] = wkp; }
            __syncthreads();            // B1

            // ---- phase 2: fold, speculate row, post fp64 candidates ----
            uint4 ma = *(const uint4*)&swm[0];
            uint4 pa = *(const uint4*)&swp[0];
            unsigned gm_ = umin(umin(ma.x, ma.y), umin(ma.z, ma.w));
            unsigned gp_ = umin(umin(pa.x, pa.y), umin(pa.z, pa.w));

            int gj = (int)(gp_ & 0x7FFu);             // fp32 argmin col (exact)
            int pg = p[gj];
            int spec = (pg == 0) ? ((i < na) ? (i + 1) : i0) : pg;

            float thr = finv(gm_) + 1e-3f;            // exact fp32 min + margin
            if (m <= thr) {                           // fast thread-level reject
                #pragma unroll
                for (int k = 0; k < CP; k++) {
                    if (c[k] <= thr) {
                        int col = (k >> 2)*CHW + cbase + (k & 3);
                        double cd = ((double)r[k] - ui) - v[col];   // exact ref order
                        cval[col] = cd;               // race-free (distinct cols)
                        atomicMin(&slot[it & 1], (dkey(cd) & ~0x7FFull) | (u64)col);
                    }
                }
            }
            if (tid == 0) slot[(it + 1) & 1] = ~0ull; // reset other slot

            {                                          // speculative row load into r[]
                const float* rs = CT + (size_t)(spec - 1) * QQ;
                #pragma unroll
                for (int ch = 0; ch < NCH; ch++) {
                    float4 t = *(const float4*)(rs + ch*CHW + cbase);
                    r[ch*4+0] = t.x; r[ch*4+1] = t.y; r[ch*4+2] = t.z; r[ch*4+3] = t.w;
                }
                pre_i0 = spec;
            }
            __syncthreads();            // B2

            // ---- phase 3: decode winner; update redundant state ----
            u64 win = slot[it & 1];
            it++;
            int bj = (int)(win & 0x7FFull);
            bool hit = (bj == gj);
            int pb = hit ? pg : p[bj];
            if (tid == 0) sdelta[cnt - 1] = cval[bj];  // tid0 only, off critical path

            if (pb == 0) {
                fbj = bj;               // way==0 => single-step backtrack
                break;                  // r[] holds next search's row if hit
            }
            if (tid == 0) ulist[cnt] = (unsigned short)bj;
            cnt++;
            i0 = pb;
            ui = u[pb];                 // consumed only by next phase-2 posts
            {                            // mark used locally if one of my cols
                int o = bj - cbase;
                #pragma unroll
                for (int k = 0; k < CP; k++)
                    if (o == (k >> 2)*CHW + (k & 3)) w[k] = -FLT_MAX;
            }
        }

        __syncthreads();                // S1: ulist/sdelta writes visible

        // ---- parallel bit-exact write-back: entry k gets deltas k..cnt-1 ----
        if (tid < cnt) {
            if (tid == 0) {              // dummy column: u[i] only (v[dummy] never read)
                double uu = u[i];
                for (int t = 0; t < cnt; t++) uu += sdelta[t];
                u[i] = uu;
            } else {
                int col = ulist[tid];
                int ik = p[col];
                double uu = u[ik];
                double vv = v[col];
                for (int t = tid; t < cnt; t++) {     // ascending t == reference order
                    double d = sdelta[t];
                    uu += d;
                    vv -= d;
                }
                u[ik] = uu;
                v[col] = vv;
                vf[col] = (float)vv;     // restore shadow master
            }
        }
        if (tid == 0) p[fbj] = (short)i;              // assign final unmatched column
        __syncthreads();                // S2: write-back visible

        // refresh register shadow (clears sentinels, picks up new v values)
        #pragma unroll
        for (int ch = 0; ch < NCH; ch++) {
            float4 t = *(const float4*)(vf + ch*CHW + cbase);
            w[ch*4+0] = t.x; w[ch*4+1] = t.y; w[ch*4+2] = t.z; w[ch*4+3] = t.w;
        }
    }

    // outputs: proposal col matched to gt p[col]-1
    for (int jj = tid; jj < QQ; jj += NT) {
        int pj = p[jj];
        size_t o = (size_t)b * QQ + jj;
        out_inds[o] = (pj > 0) ? (float)(pj - 1) : 0.0f;
        out_mask[o] = (pj > 0) ? 1.0f : 0.0f;
    }
}

// ---------------- launch ------------------------------------------------
extern "C" void kernel_launch(void* const* d_in, const int* in_sizes, int n_in,
                              void* d_out, int out_size) {
    const float* sem    = (const float*)d_in[0];
    const float* center = (const float*)d_in[1];
    const float* sizes  = (const float*)d_in[2];
    const float* gious  = (const float*)d_in[3];
    const int*   labels = (const int*)d_in[4];
    const int*   na     = (const int*)d_in[5];

    float* out      = (float*)d_out;
    float* out_inds = out;
    float* out_mask = out + (size_t)BB * QQ;
    float* fc       = out + (size_t)2 * BB * QQ;   // final_cost region

    prep_kernel<<<1, 512>>>(labels, na);
    cost_transpose_kernel<<<dim3(QQ/32, GG/32, BB), dim3(32, 8)>>>(sem, center, sizes, gious, fc);
    lsa_kernel<<<BB, NT>>>(out_inds, out_mask);
}

// round 14
// speedup vs baseline: 1.0612x; 1.0012x over previous
#include <cuda_runtime.h>
#include <math.h>
#include <cfloat>

#define BB 8
#define QQ 2048
#define GG 128
#define CC 512
#define NT 128
#define NW (NT/32)           // 4 warps
#define NCH 4                // column chunks (512 cols each)
#define CHW 512              // chunk width
#define CP 16                // columns per thread (4 chunks x 4 contiguous)
#define MAXPATH 140          // path entries: dummy + <=G matched + slack

typedef unsigned long long u64;

// ---------------- device scratch (no allocation allowed) ----------------
__device__ float g_ct[BB*GG*QQ];   // transposed cost: CT[b][g][q]  (8 MB)

// ------- fused cost + transpose (with inline int64/int32 label detect) ------
__global__ void cost_transpose_kernel(const float* __restrict__ sem,
                                      const float* __restrict__ center,
                                      const float* __restrict__ sizes,
                                      const float* __restrict__ gious,
                                      const int* __restrict__ lab_raw,
                                      float* __restrict__ fc) {
    __shared__ float tile[32][33];
    int b = blockIdx.z;
    int q0 = blockIdx.x * 32, g0 = blockIdx.y * 32;
    int x = threadIdx.x;
    int t = threadIdx.y * 32 + x;      // 0..255

    // detect label width: values in [0,512) so int64 high words are all 0;
    // probe only the first half of the element count (safe for int32 buffers)
    int nz = 0;
    for (int k = t; k < (BB*GG)/2; k += 256)
        nz |= (lab_raw[2*k + 1] != 0);
    bool l64 = (__syncthreads_or(nz) == 0);

    int g = g0 + x;
    int li = b*GG + g;
    int lab = l64 ? lab_raw[2*li] : lab_raw[li];
    for (int r = threadIdx.y; r < 32; r += 8) {
        int q = q0 + r;
        float s = sem[((size_t)(b*QQ + q))*CC + lab];
        // XLA lowers lax.logistic as 0.5 + 0.5*tanh(0.5*x)
        float p = 0.5f + 0.5f * tanhf(0.5f * s);
        float pos = 0.25f * (1.0f - p) * (1.0f - p) * (-logf(p + 1e-8f));
        float neg = 0.75f * p * p * (-log1pf(-(p - 1e-8f)));
        float diff = pos - neg;
        size_t idx = ((size_t)(b*QQ + q))*GG + g;
        float val = 2.0f*diff + 5.0f*center[idx] + 1.0f*sizes[idx] - 2.0f*gious[idx];
        fc[idx] = val;                 // coalesced along g
        tile[r][x] = val;
    }
    __syncthreads();
    for (int r = threadIdx.y; r < 32; r += 8)
        g_ct[((size_t)(b*GG + g0 + r))*QQ + q0 + x] = tile[x][r];  // coalesced along q
}

// --------- order-preserving keys (monotone) -----------------------------
__device__ __forceinline__ unsigned fkey(float f) {
    unsigned u = __float_as_uint(f);
    return (u & 0x80000000u) ? ~u : (u | 0x80000000u);
}
__device__ __forceinline__ float finv(unsigned k) {
    unsigned u = (k & 0x80000000u) ? (k & 0x7fffffffu) : ~k;
    return __uint_as_float(u);
}
__device__ __forceinline__ u64 dkey(double d) {
    u64 b = (u64)__double_as_longlong(d);
    return (b & 0x8000000000000000ull) ? ~b : (b | 0x8000000000000000ull);
}

// ---------------- LSA: exact replica of the reference's algorithm -------
// R10 structure verbatim (two exact-key REDUX, balanced trees, atomicMin-
// u64 winner, 2 barriers, speculative row prefetch, lazy-delta bit-exact
// write-back) with ONE change: the per-row-constant u[i0] term is removed
// from the fp32 scan (cannot change argmin or the min-relative candidate
// set; the exact fp64 verification still includes u[i0] and is unchanged).
__global__ void __launch_bounds__(NT, 1) lsa_kernel(const int* __restrict__ na_raw,
                                                    float* __restrict__ out_inds,
                                                    float* __restrict__ out_mask) {
    __shared__ double v[QQ];            // fp64 master potentials (0-based cols)
    __shared__ __align__(16) float vf[QQ];  // fp32 shadow master
    __shared__ double u[GG + 1];        // rows 1..GG
    __shared__ short  p[QQ];            // matched row per col (0 = free)
    __shared__ unsigned short ulist[MAXPATH];
    __shared__ double sdelta[MAXPATH];
    __shared__ __align__(16) unsigned swm[NW];   // per-warp exact fp32 min key
    __shared__ __align__(16) unsigned swp[NW];   // per-warp (key21|col11) min
    __shared__ double cval[QQ];         // exact fp64 reduced cost of posted cols
    __shared__ u64 slot[2];             // ping-pong winner keys

    int b = blockIdx.x;
    int tid = threadIdx.x;
    int lane = tid & 31, wid = tid >> 5;
    const float* CT = g_ct + (size_t)b * GG * QQ;
    const int cbase = tid << 2;         // my 4 cols within each chunk start here

    // detect nactual_gt width (values in [1,128]; probe first half only)
    int nzv = 0;
    for (int k = tid; k < BB/2; k += NT)
        nzv |= (na_raw[2*k + 1] != 0);
    bool n64 = (__syncthreads_or(nzv) == 0);
    int na = n64 ? na_raw[2*b] : na_raw[b];
    if (na < 0) na = 0;
    if (na > GG) na = GG;

    for (int jj = tid; jj < QQ; jj += NT) { v[jj] = 0.0; vf[jj] = 0.0f; p[jj] = 0; }
    for (int jj = tid; jj <= GG; jj += NT) u[jj] = 0.0;
    if (tid == 0) { ulist[0] = 0; slot[0] = ~0ull; slot[1] = ~0ull; }
    __syncthreads();

    float r[CP], w[CP], c[CP];
    #pragma unroll
    for (int k = 0; k < CP; k++) { r[k] = 0.f; w[k] = 0.f; }
    int pre_i0 = -1;
    int it = 0;                         // global iteration parity counter

    if (na > 0) {                        // warm prefetch: row 1
        #pragma unroll
        for (int ch = 0; ch < NCH; ch++) {
            float4 t = *(const float4*)(CT + ch*CHW + cbase);
            r[ch*4+0] = t.x; r[ch*4+1] = t.y; r[ch*4+2] = t.z; r[ch*4+3] = t.w;
        }
        pre_i0 = 1;
    }

    for (int i = 1; i <= na; i++) {
        int cnt = 1;                    // path length incl. dummy (redundant)
        int i0 = i;
        double ui = u[i];               // used only by fp64 candidate posts
        int fbj = 0;

        for (;;) {
            if (pre_i0 != i0) {         // mispredict: synchronous reload (uniform)
                const float* row = CT + (size_t)(i0 - 1) * QQ;
                #pragma unroll
                for (int ch = 0; ch < NCH; ch++) {
                    float4 t = *(const float4*)(row + ch*CHW + cbase);
                    r[ch*4+0] = t.x; r[ch*4+1] = t.y; r[ch*4+2] = t.z; r[ch*4+3] = t.w;
                }
                pre_i0 = i0;
            }

            // ---- phase 1: register scan (no u term) + balanced trees ----
            #pragma unroll
            for (int k = 0; k < CP; k++) c[k] = r[k] - w[k];
            float t8[8];
            #pragma unroll
            for (int k = 0; k < 8; k++) t8[k] = fminf(c[2*k], c[2*k+1]);
            float t4a = fminf(t8[0], t8[1]), t4b = fminf(t8[2], t8[3]);
            float t4c = fminf(t8[4], t8[5]), t4d = fminf(t8[6], t8[7]);
            float m = fminf(fminf(t4a, t4b), fminf(t4c, t4d));
            int e[CP];
            #pragma unroll
            for (int k = 0; k < CP; k++) {
                int col = (k >> 2)*CHW + cbase + (k & 3);
                e[k] = (c[k] == m) ? col : 0x7FF;
            }
            int s8[8];
            #pragma unroll
            for (int k = 0; k < 8; k++) s8[k] = min(e[2*k], e[2*k+1]);
            int s4a = min(s8[0], s8[1]), s4b = min(s8[2], s8[3]);
            int s4c = min(s8[4], s8[5]), s4d = min(s8[6], s8[7]);
            int mj = min(min(s4a, s4b), min(s4c, s4d));

            unsigned km = fkey(m);
            unsigned kp = (km & 0xFFFFF800u) | (unsigned)mj;  // 21b key | 11b col
            unsigned wkm = __reduce_min_sync(0xffffffffu, km);
            unsigned wkp = __reduce_min_sync(0xffffffffu, kp);
            if (lane == 0) { swm[wid] = wkm; swp[wid] = wkp; }
            __syncthreads();            // B1

            // ---- phase 2: fold, speculate row, post fp64 candidates ----
            uint4 ma = *(const uint4*)&swm[0];
            uint4 pa = *(const uint4*)&swp[0];
            unsigned gm_ = umin(umin(ma.x, ma.y), umin(ma.z, ma.w));
            unsigned gp_ = umin(umin(pa.x, pa.y), umin(pa.z, pa.w));

            int gj = (int)(gp_ & 0x7FFu);             // fp32 argmin col (exact)
            int pg = p[gj];
            int spec = (pg == 0) ? ((i < na) ? (i + 1) : i0) : pg;

            float thr = finv(gm_) + 1e-3f;            // exact fp32 min + margin
            if (m <= thr) {                           // fast thread-level reject
                #pragma unroll
                for (int k = 0; k < CP; k++) {
                    if (c[k] <= thr) {
                        int col = (k >> 2)*CHW + cbase + (k & 3);
                        double cd = ((double)r[k] - ui) - v[col];   // exact ref order
                        cval[col] = cd;               // race-free (distinct cols)
                        atomicMin(&slot[it & 1], (dkey(cd) & ~0x7FFull) | (u64)col);
                    }
                }
            }
            if (tid == 0) slot[(it + 1) & 1] = ~0ull; // reset other slot

            {                                          // speculative row load into r[]
                const float* rs = CT + (size_t)(spec - 1) * QQ;
                #pragma unroll
                for (int ch = 0; ch < NCH; ch++) {
                    float4 t = *(const float4*)(rs + ch*CHW + cbase);
                    r[ch*4+0] = t.x; r[ch*4+1] = t.y; r[ch*4+2] = t.z; r[ch*4+3] = t.w;
                }
                pre_i0 = spec;
            }
            __syncthreads();            // B2

            // ---- phase 3: decode winner; update redundant state ----
            u64 win = slot[it & 1];
            it++;
            int bj = (int)(win & 0x7FFull);
            int pb = p[bj];
            if (tid == 0) sdelta[cnt - 1] = cval[bj];  // tid0 only, off critical path

            if (pb == 0) {
                fbj = bj;               // way==0 => single-step backtrack
                break;                  // r[] holds next search's row if predicted
            }
            if (tid == 0) ulist[cnt] = (unsigned short)bj;
            cnt++;
            i0 = pb;
            ui = u[pb];                 // consumed only by next phase-2 posts
            {                            // mark used locally if one of my cols
                int o = bj - cbase;
                #pragma unroll
                for (int k = 0; k < CP; k++)
                    if (o == (k >> 2)*CHW + (k & 3)) w[k] = -FLT_MAX;
            }
        }

        __syncthreads();                // S1: ulist/sdelta writes visible

        // ---- parallel bit-exact write-back: entry k gets deltas k..cnt-1 ----
        if (tid < cnt) {
            if (tid == 0) {              // dummy column: u[i] only (v[dummy] never read)
                double uu = u[i];
                for (int t = 0; t < cnt; t++) uu += sdelta[t];
                u[i] = uu;
            } else {
                int col = ulist[tid];
                int ik = p[col];
                double uu = u[ik];
                double vv = v[col];
                for (int t = tid; t < cnt; t++) {     // ascending t == reference order
                    double d = sdelta[t];
                    uu += d;
                    vv -= d;
                }
                u[ik] = uu;
                v[col] = vv;
                vf[col] = (float)vv;     // restore shadow master
            }
        }
        if (tid == 0) p[fbj] = (short)i;              // assign final unmatched column
        __syncthreads();                // S2: write-back visible

        // refresh register shadow (clears sentinels, picks up new v values)
        #pragma unroll
        for (int ch = 0; ch < NCH; ch++) {
            float4 t = *(const float4*)(vf + ch*CHW + cbase);
            w[ch*4+0] = t.x; w[ch*4+1] = t.y; w[ch*4+2] = t.z; w[ch*4+3] = t.w;
        }
    }

    // outputs: proposal col matched to gt p[col]-1
    for (int jj = tid; jj < QQ; jj += NT) {
        int pj = p[jj];
        size_t o = (size_t)b * QQ + jj;
        out_inds[o] = (pj > 0) ? (float)(pj - 1) : 0.0f;
        out_mask[o] = (pj > 0) ? 1.0f : 0.0f;
    }
}

// ---------------- launch ------------------------------------------------
extern "C" void kernel_launch(void* const* d_in, const int* in_sizes, int n_in,
                              void* d_out, int out_size) {
    const float* sem    = (const float*)d_in[0];
    const float* center = (const float*)d_in[1];
    const float* sizes  = (const float*)d_in[2];
    const float* gious  = (const float*)d_in[3];
    const int*   labels = (const int*)d_in[4];
    const int*   na     = (const int*)d_in[5];

    float* out      = (float*)d_out;
    float* out_inds = out;
    float* out_mask = out + (size_t)BB * QQ;
    float* fc       = out + (size_t)2 * BB * QQ;   // final_cost region

    cost_transpose_kernel<<<dim3(QQ/32, GG/32, BB), dim3(32, 8)>>>(sem, center, sizes, gious, labels, fc);
    lsa_kernel<<<BB, NT>>>(na, out_inds, out_mask);
}

// round 16
// speedup vs baseline: 1.0759x; 1.0138x over previous
#include <cuda_runtime.h>
#include <math.h>
#include <cfloat>

#define BB 8
#define QQ 2048
#define GG 128
#define CC 512
#define NT 128
#define NW (NT/32)           // 4 warps
#define NCH 4                // column chunks (512 cols each)
#define CHW 512              // chunk width
#define CP 16                // columns per thread (4 chunks x 4 contiguous)
#define MAXPATH 140          // path entries: dummy + <=G matched + slack

typedef unsigned long long u64;

// ---------------- device scratch (no allocation allowed) ----------------
__device__ float g_ct[BB*GG*QQ];   // transposed cost: CT[b][g][q]  (8 MB)

// ------- fused cost + transpose (with inline int64/int32 label detect) ------
__global__ void cost_transpose_kernel(const float* __restrict__ sem,
                                      const float* __restrict__ center,
                                      const float* __restrict__ sizes,
                                      const float* __restrict__ gious,
                                      const int* __restrict__ lab_raw,
                                      float* __restrict__ fc) {
    __shared__ float tile[32][33];
    int b = blockIdx.z;
    int q0 = blockIdx.x * 32, g0 = blockIdx.y * 32;
    int x = threadIdx.x;
    int t = threadIdx.y * 32 + x;      // 0..255

    // detect label width: values in [0,512) so int64 high words are all 0;
    // probe only the first half of the element count (safe for int32 buffers)
    int nz = 0;
    for (int k = t; k < (BB*GG)/2; k += 256)
        nz |= (lab_raw[2*k + 1] != 0);
    bool l64 = (__syncthreads_or(nz) == 0);

    int g = g0 + x;
    int li = b*GG + g;
    int lab = l64 ? lab_raw[2*li] : lab_raw[li];
    for (int r = threadIdx.y; r < 32; r += 8) {
        int q = q0 + r;
        float s = sem[((size_t)(b*QQ + q))*CC + lab];
        // XLA lowers lax.logistic as 0.5 + 0.5*tanh(0.5*x)
        float p = 0.5f + 0.5f * tanhf(0.5f * s);
        float pos = 0.25f * (1.0f - p) * (1.0f - p) * (-logf(p + 1e-8f));
        float neg = 0.75f * p * p * (-log1pf(-(p - 1e-8f)));
        float diff = pos - neg;
        size_t idx = ((size_t)(b*QQ + q))*GG + g;
        float val = 2.0f*diff + 5.0f*center[idx] + 1.0f*sizes[idx] - 2.0f*gious[idx];
        fc[idx] = val;                 // coalesced along g
        tile[r][x] = val;
    }
    __syncthreads();
    for (int r = threadIdx.y; r < 32; r += 8)
        g_ct[((size_t)(b*GG + g0 + r))*QQ + q0 + x] = tile[x][r];  // coalesced along q
}

// --------- order-preserving keys (monotone) -----------------------------
__device__ __forceinline__ unsigned fkey(float f) {
    unsigned u = __float_as_uint(f);
    return (u & 0x80000000u) ? ~u : (u | 0x80000000u);
}
__device__ __forceinline__ float finv(unsigned k) {
    unsigned u = (k & 0x80000000u) ? (k & 0x7fffffffu) : ~k;
    return __uint_as_float(u);
}
__device__ __forceinline__ u64 dkey(double d) {
    u64 b = (u64)__double_as_longlong(d);
    return (b & 0x8000000000000000ull) ? ~b : (b | 0x8000000000000000ull);
}

// ---------------- LSA: exact replica of the reference's algorithm -------
// R10 lsa verbatim (the 164us-measured config): fp32 scan WITH the u term
// (cancellation keeps the comparison grid fine near the min), two exact-key
// REDUX, balanced min/argmin trees, atomicMin-u64 winner with warp-1 slot
// reset, 2 barriers/iteration, speculative row prefetch, lazy-delta
// bit-exact write-back. Only change: na width detection inlined (prep
// kernel deleted).
__global__ void __launch_bounds__(NT, 1) lsa_kernel(const int* __restrict__ na_raw,
                                                    float* __restrict__ out_inds,
                                                    float* __restrict__ out_mask) {
    __shared__ double v[QQ];            // fp64 master potentials (0-based cols)
    __shared__ __align__(16) float vf[QQ];  // fp32 shadow master
    __shared__ double u[GG + 1];        // rows 1..GG
    __shared__ short  p[QQ];            // matched row per col (0 = free)
    __shared__ unsigned short ulist[MAXPATH];
    __shared__ double sdelta[MAXPATH];
    __shared__ __align__(16) unsigned swm[NW];   // per-warp exact fp32 min key
    __shared__ __align__(16) unsigned swp[NW];   // per-warp (key21|col11) min
    __shared__ double cval[QQ];         // exact fp64 reduced cost of posted cols
    __shared__ u64 slot[2];             // ping-pong winner keys

    int b = blockIdx.x;
    int tid = threadIdx.x;
    int lane = tid & 31, wid = tid >> 5;
    const float* CT = g_ct + (size_t)b * GG * QQ;
    const int cbase = tid << 2;         // my 4 cols within each chunk start here

    // detect nactual_gt width (values in [1,128]; probe first half only)
    int nzv = 0;
    for (int k = tid; k < BB/2; k += NT)
        nzv |= (na_raw[2*k + 1] != 0);
    bool n64 = (__syncthreads_or(nzv) == 0);
    int na = n64 ? na_raw[2*b] : na_raw[b];
    if (na < 0) na = 0;
    if (na > GG) na = GG;

    for (int jj = tid; jj < QQ; jj += NT) { v[jj] = 0.0; vf[jj] = 0.0f; p[jj] = 0; }
    for (int jj = tid; jj <= GG; jj += NT) u[jj] = 0.0;
    if (tid == 0) { ulist[0] = 0; slot[0] = ~0ull; slot[1] = ~0ull; }
    __syncthreads();

    float r[CP], w[CP], c[CP];
    #pragma unroll
    for (int k = 0; k < CP; k++) { r[k] = 0.f; w[k] = 0.f; }
    int pre_i0 = -1;
    int it = 0;                         // global iteration parity counter

    if (na > 0) {                        // warm prefetch: row 1
        #pragma unroll
        for (int ch = 0; ch < NCH; ch++) {
            float4 t = *(const float4*)(CT + ch*CHW + cbase);
            r[ch*4+0] = t.x; r[ch*4+1] = t.y; r[ch*4+2] = t.z; r[ch*4+3] = t.w;
        }
        pre_i0 = 1;
    }

    for (int i = 1; i <= na; i++) {
        int cnt = 1;                    // path length incl. dummy (redundant)
        int i0 = i;
        double ui = u[i];
        float uif = (float)ui;
        int fbj = 0;

        for (;;) {
            if (pre_i0 != i0) {         // mispredict: synchronous reload (uniform)
                const float* row = CT + (size_t)(i0 - 1) * QQ;
                #pragma unroll
                for (int ch = 0; ch < NCH; ch++) {
                    float4 t = *(const float4*)(row + ch*CHW + cbase);
                    r[ch*4+0] = t.x; r[ch*4+1] = t.y; r[ch*4+2] = t.z; r[ch*4+3] = t.w;
                }
                pre_i0 = i0;
            }

            // ---- phase 1: register scan + balanced min / argmin trees ----
            #pragma unroll
            for (int k = 0; k < CP; k++) c[k] = (r[k] - uif) - w[k];
            float t8[8];
            #pragma unroll
            for (int k = 0; k < 8; k++) t8[k] = fminf(c[2*k], c[2*k+1]);
            float t4a = fminf(t8[0], t8[1]), t4b = fminf(t8[2], t8[3]);
            float t4c = fminf(t8[4], t8[5]), t4d = fminf(t8[6], t8[7]);
            float m = fminf(fminf(t4a, t4b), fminf(t4c, t4d));
            int e[CP];
            #pragma unroll
            for (int k = 0; k < CP; k++) {
                int col = (k >> 2)*CHW + cbase + (k & 3);
                e[k] = (c[k] == m) ? col : 0x7FF;
            }
            int s8[8];
            #pragma unroll
            for (int k = 0; k < 8; k++) s8[k] = min(e[2*k], e[2*k+1]);
            int s4a = min(s8[0], s8[1]), s4b = min(s8[2], s8[3]);
            int s4c = min(s8[4], s8[5]), s4d = min(s8[6], s8[7]);
            int mj = min(min(s4a, s4b), min(s4c, s4d));

            unsigned km = fkey(m);
            unsigned kp = (km & 0xFFFFF800u) | (unsigned)mj;  // 21b key | 11b col
            unsigned wkm = __reduce_min_sync(0xffffffffu, km);
            unsigned wkp = __reduce_min_sync(0xffffffffu, kp);
            if (lane == 0) { swm[wid] = wkm; swp[wid] = wkp; }
            __syncthreads();            // B1

            // ---- phase 2: fold, post candidates, speculative load into r[] ----
            uint4 ma = *(const uint4*)&swm[0];
            uint4 pa = *(const uint4*)&swp[0];
            unsigned gm_ = umin(umin(ma.x, ma.y), umin(ma.z, ma.w));
            unsigned gp_ = umin(umin(pa.x, pa.y), umin(pa.z, pa.w));

            int gj = (int)(gp_ & 0x7FFu);             // fp32 argmin col (exact)
            int pg = p[gj];
            int spec = (pg == 0) ? ((i < na) ? (i + 1) : i0) : pg;

            float thr = finv(gm_) + 1e-3f;            // exact fp32 min + margin
            if (m <= thr) {                           // fast thread-level reject
                double uid = ui;
                #pragma unroll
                for (int k = 0; k < CP; k++) {
                    if (c[k] <= thr) {
                        int col = (k >> 2)*CHW + cbase + (k & 3);
                        double cd = ((double)r[k] - uid) - v[col];
                        cval[col] = cd;               // exact value (distinct cols)
                        atomicMin(&slot[it & 1], (dkey(cd) & ~0x7FFull) | (u64)col);
                    }
                }
            }
            if (tid == 32) slot[(it + 1) & 1] = ~0ull;  // reset other slot (warp 1)

            {                                          // speculative row load into r[]
                const float* rs = CT + (size_t)(spec - 1) * QQ;
                #pragma unroll
                for (int ch = 0; ch < NCH; ch++) {
                    float4 t = *(const float4*)(rs + ch*CHW + cbase);
                    r[ch*4+0] = t.x; r[ch*4+1] = t.y; r[ch*4+2] = t.z; r[ch*4+3] = t.w;
                }
                pre_i0 = spec;
            }
            __syncthreads();            // B2

            // ---- phase 3: decode winner (3 LDS), update redundant state ----
            u64 win = slot[it & 1];
            it++;
            int bj = (int)(win & 0x7FFull);
            double delta = cval[bj];                   // exact fp64 of chosen col
            if (tid == 0) sdelta[cnt - 1] = delta;     // delta of step cnt-1
            int pb = p[bj];

            if (pb == 0) {
                fbj = bj;               // way==0 => single-step backtrack
                break;                  // r[] already holds the speculated next row
            }
            if (tid == 0) ulist[cnt] = (unsigned short)bj;  // joins at step cnt
            cnt++;
            i0 = pb;
            ui = u[pb];
            uif = (float)ui;
            {                            // mark used locally if one of my cols
                int o = bj - cbase;
                #pragma unroll
                for (int k = 0; k < CP; k++)
                    if (o == (k >> 2)*CHW + (k & 3)) w[k] = -FLT_MAX;
            }
        }

        __syncthreads();                // S1: ulist/sdelta writes visible

        // ---- parallel bit-exact write-back: entry k gets deltas k..cnt-1 ----
        if (tid < cnt) {
            if (tid == 0) {              // dummy column: u[i] only (v[dummy] never read)
                double uu = u[i];
                for (int t = 0; t < cnt; t++) uu += sdelta[t];
                u[i] = uu;
            } else {
                int col = ulist[tid];
                int ik = p[col];
                double uu = u[ik];
                double vv = v[col];
                for (int t = tid; t < cnt; t++) {     // ascending t == reference order
                    double d = sdelta[t];
                    uu += d;
                    vv -= d;
                }
                u[ik] = uu;
                v[col] = vv;
                vf[col] = (float)vv;     // restore shadow master
            }
        }
        if (tid == 0) p[fbj] = (short)i;              // assign final unmatched column
        __syncthreads();                // S2: write-back visible

        // refresh register shadow (clears sentinels, picks up new v values)
        #pragma unroll
        for (int ch = 0; ch < NCH; ch++) {
            float4 t = *(const float4*)(vf + ch*CHW + cbase);
            w[ch*4+0] = t.x; w[ch*4+1] = t.y; w[ch*4+2] = t.z; w[ch*4+3] = t.w;
        }
    }

    // outputs: proposal col matched to gt p[col]-1
    for (int jj = tid; jj < QQ; jj += NT) {
        int pj = p[jj];
        size_t o = (size_t)b * QQ + jj;
        out_inds[o] = (pj > 0) ? (float)(pj - 1) : 0.0f;
        out_mask[o] = (pj > 0) ? 1.0f : 0.0f;
    }
}

// ---------------- launch ------------------------------------------------
extern "C" void kernel_launch(void* const* d_in, const int* in_sizes, int n_in,
                              void* d_out, int out_size) {
    const float* sem    = (const float*)d_in[0];
    const float* center = (const float*)d_in[1];
    const float* sizes  = (const float*)d_in[2];
    const float* gious  = (const float*)d_in[3];
    const int*   labels = (const int*)d_in[4];
    const int*   na     = (const int*)d_in[5];

    float* out      = (float*)d_out;
    float* out_inds = out;
    float* out_mask = out + (size_t)BB * QQ;
    float* fc       = out + (size_t)2 * BB * QQ;   // final_cost region

    cost_transpose_kernel<<<dim3(QQ/32, GG/32, BB), dim3(32, 8)>>>(sem, center, sizes, gious, labels, fc);
    lsa_kernel<<<BB, NT>>>(na, out_inds, out_mask);
}